// round 15
// baseline (speedup 1.0000x reference)
#include <cuda_runtime.h>

#define NS 64      // states
#define NE 128     // edges = 2*NS
#define ROWS 4     // batch rows per warp
#define THREADS 256

// Fixed trellis structure (from the problem's _build_matrices):
//   src(e) = tflat[e] = 2*((e>>1)&31) + (e&1).
// mask is the 0/1 indicator of exactly this pattern, so
//   w[e] = sum_s s2e[s,e]*mask[s,e] = s2e[src(e),e]*mask[src(e),e].
// Values in s2e / l2e stay fully general (learnable).
//
// All hot-path indices fit in 32 bits (largest element index = batch*32 < 2^31).

__global__ void __launch_bounds__(THREADS)
acs_kernel(const float4* __restrict__ prob4,   // in_prob as [B*16] float4
           const float2* __restrict__ llrs2,   // llrs    as [B]    float2
           const float*  __restrict__ s2e,     // [64, 128]
           const float*  __restrict__ mask,    // [64, 128]
           const float*  __restrict__ l2e,     // [2, 128]
           float2* __restrict__ outm2,         // max as [B*32] float2
           float2* __restrict__ outi2,         // ind as [B*32] float2
           int batch)
{
    __shared__ __align__(16) float sh_w[NE];        // collapsed edge weights
    __shared__ __align__(16) float sh_c[2 * NE];    // l2e rows

    const unsigned tid  = threadIdx.x;
    const unsigned lane = tid & 31u;

    // Stage per-edge constants once per block (coalesced).
    if (tid < NE) {
        const int e = (int)tid;
        const int s = 2 * ((e >> 1) & 31) + (e & 1);   // src(e)
        sh_w[e] = s2e[s * NE + e] * mask[s * NE + e];
    }
    sh_c[tid] = l2e[tid];                               // 256 == 2*NE
    __syncthreads();

    const unsigned wid  = blockIdx.x * (THREADS / 32u) + (tid >> 5);
    const unsigned row0 = wid * ROWS;
    if (row0 >= (unsigned)batch) return;

    // Per-lane constants for edges 4l..4l+3 (conflict-free LDS.128).
    const float4 w4 = ((const float4*)sh_w)[lane];
    const float4 c0 = ((const float4*)sh_c)[lane];
    const float4 c1 = ((const float4*)(sh_c + NE))[lane];
    const unsigned pidx = lane & 15u;

    if (row0 + ROWS <= (unsigned)batch) {
        // ---- Hot path: guard-free, fully front-batched ----
        float4 p[ROWS];
        float2 L[ROWS];
        #pragma unroll
        for (unsigned r = 0; r < ROWS; r++) {
            const unsigned row = row0 + r;
            p[r] = __ldcs(&prob4[row * 16u + pidx]);   // 16 unique float4/row
            L[r] = __ldcs(&llrs2[row]);                // warp-broadcast
        }

        #pragma unroll
        for (unsigned r = 0; r < ROWS; r++) {
            const unsigned o = (row0 + r) * 32u + lane;

            const float b0 = fmaf(L[r].x, c0.x, L[r].y * c1.x);
            const float b1 = fmaf(L[r].x, c0.y, L[r].y * c1.y);
            const float b2 = fmaf(L[r].x, c0.z, L[r].y * c1.z);
            const float b3 = fmaf(L[r].x, c0.w, L[r].y * c1.w);

            const float x0 = fmaf(p[r].x, w4.x, b0);
            const float x1 = fmaf(p[r].y, w4.y, b1);
            const float x2 = fmaf(p[r].z, w4.z, b2);
            const float x3 = fmaf(p[r].w, w4.w, b3);

            float2 mx, id;
            mx.x = fmaxf(x0, x1); id.x = (x1 > x0) ? 1.0f : 0.0f;  // tie -> 0
            mx.y = fmaxf(x2, x3); id.y = (x3 > x2) ? 1.0f : 0.0f;

            __stcs(&outm2[o], mx);   // write-once: evict-first
            __stcs(&outi2[o], id);
        }
    } else {
        // ---- Tail (inactive for batch % 4 == 0, kept for generality) ----
        const unsigned nr = (unsigned)batch - row0;
        for (unsigned r = 0; r < nr; r++) {
            const unsigned row = row0 + r;
            const float4 pr = __ldcs(&prob4[row * 16u + pidx]);
            const float2 Lr = __ldcs(&llrs2[row]);

            const float x0 = fmaf(pr.x, w4.x, fmaf(Lr.x, c0.x, Lr.y * c1.x));
            const float x1 = fmaf(pr.y, w4.y, fmaf(Lr.x, c0.y, Lr.y * c1.y));
            const float x2 = fmaf(pr.z, w4.z, fmaf(Lr.x, c0.z, Lr.y * c1.z));
            const float x3 = fmaf(pr.w, w4.w, fmaf(Lr.x, c0.w, Lr.y * c1.w));

            float2 mx, id;
            mx.x = fmaxf(x0, x1); id.x = (x1 > x0) ? 1.0f : 0.0f;
            mx.y = fmaxf(x2, x3); id.y = (x3 > x2) ? 1.0f : 0.0f;

            const unsigned o = row * 32u + lane;
            __stcs(&outm2[o], mx);
            __stcs(&outi2[o], id);
        }
    }
}

extern "C" void kernel_launch(void* const* d_in, const int* in_sizes, int n_in,
                              void* d_out, int out_size) {
    const float* in_prob = (const float*)d_in[0];   // [B, 64]
    const float* llrs    = (const float*)d_in[1];   // [B, 2]
    const float* s2e     = (const float*)d_in[2];   // [64, 128]
    const float* mask    = (const float*)d_in[3];   // [64, 128]
    const float* l2e     = (const float*)d_in[4];   // [2, 128]

    const int batch = in_sizes[0] / NS;

    float* out_max = (float*)d_out;                          // [B, 64]
    float* out_ind = (float*)d_out + (long long)batch * NS;  // [B, 64]

    const long long warps = ((long long)batch + ROWS - 1) / ROWS;
    const int blocks = (int)((warps + (THREADS / 32) - 1) / (THREADS / 32));

    acs_kernel<<<blocks, THREADS>>>((const float4*)in_prob,
                                    (const float2*)llrs,
                                    s2e, mask, l2e,
                                    (float2*)out_max,
                                    (float2*)out_ind,
                                    batch);
}